// round 1
// baseline (speedup 1.0000x reference)
#include <cuda_runtime.h>
#include <cuda_bf16.h>

// Problem constants (fixed by the dataset)
#define N_G  4096
#define IMG_W 512
#define TILE 64
#define NT   8          // tiles per axis
#define BLOCK 256

// Depth-sorted gaussian parameters (SoA, float4-packed)
__device__ float4 g_geo[N_G];   // px, py, radius, opacity
__device__ float4 g_con[N_G];   // ia, ib+ic, id, (pad)
__device__ float4 g_col[N_G];   // r, g, b, (pad)

// ---------------------------------------------------------------------------
// Kernel 1: stable depth-rank (O(N^2) count) + derived params, scatter to rank
// ---------------------------------------------------------------------------
__global__ void preprocess_kernel(const float* __restrict__ pos2d,   // (N,3)
                                  const float* __restrict__ cov2d,   // (N,2,2)
                                  const float* __restrict__ opacity, // (N,)
                                  const float* __restrict__ color)   // (N,3)
{
    __shared__ float sdep[BLOCK];
    const int i = blockIdx.x * BLOCK + threadIdx.x;
    const float di = pos2d[i * 3 + 2];

    int rank = 0;
    for (int base = 0; base < N_G; base += BLOCK) {
        sdep[threadIdx.x] = pos2d[(base + threadIdx.x) * 3 + 2];
        __syncthreads();
        #pragma unroll 8
        for (int j = 0; j < BLOCK; j++) {
            float dj = sdep[j];
            int g = base + j;
            // stable ascending argsort tie-break
            rank += (dj < di) || (dj == di && g < i);
        }
        __syncthreads();
    }

    // derived per-gaussian params (match reference formulas exactly)
    float a = cov2d[i * 4 + 0];
    float b = cov2d[i * 4 + 1];
    float c = cov2d[i * 4 + 2];
    float d = cov2d[i * 4 + 3];
    float trace = a + d;
    float det   = a * d - b * c;
    float disc  = fmaxf(trace * trace - 4.0f * det, 0.0f);
    float term2 = 0.5f * sqrtf(disc);
    float radius = 3.0f * sqrtf(fmaxf(0.5f * trace - term2, 0.5f * trace + term2));
    float inv_det = 1.0f / det;
    float ia  =  d * inv_det;
    float ibc = -(b + c) * inv_det;   // ib + ic
    float id_ =  a * inv_det;

    float px = pos2d[i * 3 + 0];
    float py = pos2d[i * 3 + 1];
    float op = opacity[i];
    float cr = fmaxf(color[i * 3 + 0] + 0.5f, 0.0f);
    float cg = fmaxf(color[i * 3 + 1] + 0.5f, 0.0f);
    float cb = fmaxf(color[i * 3 + 2] + 0.5f, 0.0f);

    g_geo[rank] = make_float4(px, py, radius, op);
    g_con[rank] = make_float4(ia, ibc, id_, 0.0f);
    g_col[rank] = make_float4(cr, cg, cb, 0.0f);
}

// ---------------------------------------------------------------------------
// Kernel 2: tile rasterization.
// Grid: 64 parent tiles x 16 sub-tiles (16x16 px) = 1024 blocks, 256 threads,
// one pixel per thread. Ordered ballot-compaction of the depth-sorted list
// against the PARENT 64x64 tile rect (the reference masks at parent-tile
// granularity), then sequential front-to-back compositing.
// ---------------------------------------------------------------------------
__global__ void __launch_bounds__(BLOCK) render_kernel(float* __restrict__ out)
{
    const int ptile = blockIdx.x >> 4;   // parent tile id
    const int sub   = blockIdx.x & 15;   // sub-tile within parent
    const int tx = ptile >> 3;           // tid // NT in reference
    const int ty = ptile & 7;            // tid %  NT

    const float left = (float)(tx * TILE);
    const float top  = (float)(ty * TILE);

    const int X0 = tx * TILE + ((sub >> 2) << 4);
    const int Y0 = ty * TILE + ((sub & 3) << 4);
    const int lx = threadIdx.x >> 4;
    const int ly = threadIdx.x & 15;     // consecutive threads -> consecutive Y
    const int Xi = X0 + lx;
    const int Yi = Y0 + ly;
    const float X = (float)Xi;
    const float Y = (float)Yi;

    __shared__ float s_px[BLOCK], s_py[BLOCK];
    __shared__ float s_ca[BLOCK], s_cbc[BLOCK], s_cd[BLOCK];
    __shared__ float s_op[BLOCK];
    __shared__ float s_r[BLOCK], s_g[BLOCK], s_b[BLOCK];
    __shared__ int   s_woff[BLOCK / 32];
    __shared__ int   s_cnt;

    float T = 1.0f;
    float C0 = 0.0f, C1 = 0.0f, C2 = 0.0f;
    bool dead = false;

    const int lane = threadIdx.x & 31;
    const int wid  = threadIdx.x >> 5;

    for (int base = 0; base < N_G; base += BLOCK) {
        // --- ordered compaction of this chunk against the parent-tile rect ---
        const int g = base + threadIdx.x;
        const float4 geo = g_geo[g];
        const bool valid = (geo.x + geo.z >= left) && (geo.x - geo.z < left + (float)TILE) &&
                           (geo.y + geo.z >= top)  && (geo.y - geo.z < top  + (float)TILE);
        const unsigned bits = __ballot_sync(0xffffffffu, valid);
        if (lane == 0) s_woff[wid] = __popc(bits);
        __syncthreads();
        if (threadIdx.x == 0) {
            int acc = 0;
            #pragma unroll
            for (int w = 0; w < BLOCK / 32; w++) {
                int cw = s_woff[w];
                s_woff[w] = acc;
                acc += cw;
            }
            s_cnt = acc;
        }
        __syncthreads();
        if (valid) {
            const int pos = s_woff[wid] + __popc(bits & ((1u << lane) - 1u));
            s_px[pos] = geo.x; s_py[pos] = geo.y; s_op[pos] = geo.w;
            const float4 con = g_con[g];
            s_ca[pos] = con.x; s_cbc[pos] = con.y; s_cd[pos] = con.z;
            const float4 col = g_col[g];
            s_r[pos] = col.x; s_g[pos] = col.y; s_b[pos] = col.z;
        }
        __syncthreads();

        // --- sequential front-to-back composite over compacted chunk ---
        const int cnt = s_cnt;
        if (!dead) {
            for (int j = 0; j < cnt; j++) {
                const float dx = X - s_px[j];
                const float dy = Y - s_py[j];
                const float q = s_ca[j] * dx * dx + s_cbc[j] * dx * dy + s_cd[j] * dy * dy;
                float alpha;
                if (q > 9.2104f) {
                    // op < 1 and exp(-q/2) < 0.01 => op*prob < 0.01 => clipped to floor
                    alpha = 0.01f;
                } else {
                    alpha = s_op[j] * expf(-0.5f * q);
                    alpha = fminf(fmaxf(alpha, 0.01f), 0.99f);
                }
                const float w = T * alpha;
                C0 += w * s_r[j];
                C1 += w * s_g[j];
                C2 += w * s_b[j];
                T *= (1.0f - alpha);
            }
            if (T < 1e-7f) dead = true;   // residual contribution < 1.5e-7, well under tol
        }
        // uniform early exit; also serves as the barrier before shared reuse
        if (__syncthreads_count(dead ? 0 : 1) == 0) break;
    }

    // img[X][Y][c], row-major (W, H, 3) with first axis = pixel x
    const int obase = (Xi * IMG_W + Yi) * 3;
    out[obase + 0] = C0;
    out[obase + 1] = C1;
    out[obase + 2] = C2;
}

// ---------------------------------------------------------------------------
extern "C" void kernel_launch(void* const* d_in, const int* in_sizes, int n_in,
                              void* d_out, int out_size)
{
    const float* pos2d   = (const float*)d_in[0];
    const float* cov2d   = (const float*)d_in[1];
    const float* opacity = (const float*)d_in[2];
    const float* color   = (const float*)d_in[3];
    float* out = (float*)d_out;

    preprocess_kernel<<<N_G / BLOCK, BLOCK>>>(pos2d, cov2d, opacity, color);
    render_kernel<<<(NT * NT) * 16, BLOCK>>>(out);
}

// round 2
// speedup vs baseline: 1.2746x; 1.2746x over previous
#include <cuda_runtime.h>
#include <cuda_bf16.h>

#define N_G   4096
#define IMG_W 512
#define TILE  64
#define NT    8
#define BLOCK 256
#define NJB   16                    // j-blocks for rank partials
#define EXPSCALE (-0.72134752044f)  // -0.5 * log2(e)

// depth-sorted packed gaussian params
__device__ float4 g_geo[N_G];          // px, py, radius, 0
__device__ float4 g_pa [N_G];          // px, py, ca*S, cbc*S
__device__ float4 g_pb [N_G];          // cd*S, log2(op), r, g
__device__ float  g_pc [N_G];          // b
__device__ int    g_prank[NJB][N_G];   // partial rank counts

// per-tile compacted, depth-ordered lists
__device__ float4 t_pa[64 * N_G];
__device__ float4 t_pb[64 * N_G];
__device__ float  t_pc[64 * N_G];
__device__ int    t_cnt[64];

__device__ __forceinline__ float ex2f(float x) {
    float y;
    asm("ex2.approx.f32 %0, %1;" : "=f"(y) : "f"(x));
    return y;
}

// ---------------------------------------------------------------------------
// Kernel 1: partial stable-rank counts (grid 16x16, no atomics)
// ---------------------------------------------------------------------------
__global__ void rank_partial(const float* __restrict__ pos2d)
{
    __shared__ float sdep[BLOCK];
    const int i  = blockIdx.x * BLOCK + threadIdx.x;
    const int j0 = blockIdx.y * BLOCK;
    const float di = pos2d[i * 3 + 2];
    sdep[threadIdx.x] = pos2d[(j0 + threadIdx.x) * 3 + 2];
    __syncthreads();
    int cnt = 0;
    #pragma unroll 8
    for (int j = 0; j < BLOCK; j++) {
        const float dj = sdep[j];
        cnt += (dj < di) || (dj == di && (j0 + j) < i);   // stable tie-break
    }
    g_prank[blockIdx.y][i] = cnt;
}

// ---------------------------------------------------------------------------
// Kernel 2: derive params (pre-scaled conic, log2-opacity), scatter by rank
// ---------------------------------------------------------------------------
__global__ void scatter_kernel(const float* __restrict__ pos2d,
                               const float* __restrict__ cov2d,
                               const float* __restrict__ opacity,
                               const float* __restrict__ color)
{
    const int i = blockIdx.x * BLOCK + threadIdx.x;
    int rank = 0;
    #pragma unroll
    for (int b = 0; b < NJB; b++) rank += g_prank[b][i];

    const float a = cov2d[i * 4 + 0];
    const float b = cov2d[i * 4 + 1];
    const float c = cov2d[i * 4 + 2];
    const float d = cov2d[i * 4 + 3];
    const float trace = a + d;
    const float det   = a * d - b * c;
    const float term2 = 0.5f * sqrtf(fmaxf(trace * trace - 4.0f * det, 0.0f));
    const float radius = 3.0f * sqrtf(fmaxf(0.5f * trace - term2, 0.5f * trace + term2));
    const float inv_det = 1.0f / det;
    const float ia  =  d * inv_det;
    const float ibc = -(b + c) * inv_det;
    const float id_ =  a * inv_det;

    const float px = pos2d[i * 3 + 0];
    const float py = pos2d[i * 3 + 1];
    const float op = opacity[i];
    const float lop2 = __log2f(op);            // op=0 -> -inf -> ex2 -> 0 -> clamp 0.01
    const float cr = fmaxf(color[i * 3 + 0] + 0.5f, 0.0f);
    const float cg = fmaxf(color[i * 3 + 1] + 0.5f, 0.0f);
    const float cb = fmaxf(color[i * 3 + 2] + 0.5f, 0.0f);

    g_geo[rank] = make_float4(px, py, radius, 0.0f);
    g_pa [rank] = make_float4(px, py, EXPSCALE * ia, EXPSCALE * ibc);
    g_pb [rank] = make_float4(EXPSCALE * id_, lop2, cr, cg);
    g_pc [rank] = cb;
}

// ---------------------------------------------------------------------------
// Kernel 3: per-tile binning — ordered ballot compaction into global lists
// ---------------------------------------------------------------------------
__global__ void __launch_bounds__(BLOCK) binning_kernel()
{
    const int tile = blockIdx.x;
    const int tx = tile >> 3;
    const int ty = tile & 7;
    const float left = (float)(tx * TILE);
    const float top  = (float)(ty * TILE);

    __shared__ int s_woff[BLOCK / 32];
    __shared__ int s_tot;
    const int lane = threadIdx.x & 31;
    const int wid  = threadIdx.x >> 5;

    float4* __restrict__ opa = t_pa + tile * N_G;
    float4* __restrict__ opb = t_pb + tile * N_G;
    float*  __restrict__ opc = t_pc + tile * N_G;

    int outbase = 0;
    for (int base = 0; base < N_G; base += BLOCK) {
        const int g = base + threadIdx.x;
        const float4 geo = g_geo[g];
        const bool valid = (geo.x + geo.z >= left) && (geo.x - geo.z < left + (float)TILE) &&
                           (geo.y + geo.z >= top)  && (geo.y - geo.z < top  + (float)TILE);
        const unsigned bits = __ballot_sync(0xffffffffu, valid);
        if (lane == 0) s_woff[wid] = __popc(bits);
        __syncthreads();
        if (threadIdx.x == 0) {
            int acc = 0;
            #pragma unroll
            for (int w = 0; w < BLOCK / 32; w++) { int cw = s_woff[w]; s_woff[w] = acc; acc += cw; }
            s_tot = acc;
        }
        __syncthreads();
        if (valid) {
            const int pos = outbase + s_woff[wid] + __popc(bits & ((1u << lane) - 1u));
            opa[pos] = g_pa[g];
            opb[pos] = g_pb[g];
            opc[pos] = g_pc[g];
        }
        outbase += s_tot;
        __syncthreads();
    }
    if (threadIdx.x == 0) t_cnt[tile] = outbase;
}

// ---------------------------------------------------------------------------
// Kernel 4: render. 1024 blocks (64 tiles x 16 sub-tiles of 16x16 px),
// 1 px/thread, streaming the precompacted list via broadcast L1 loads.
// No shared memory, no block syncs; per-warp early termination.
// ---------------------------------------------------------------------------
__global__ void __launch_bounds__(BLOCK) render_kernel(float* __restrict__ out)
{
    const int ptile = blockIdx.x >> 4;
    const int sub   = blockIdx.x & 15;
    const int tx = ptile >> 3;
    const int ty = ptile & 7;

    const int Xi = tx * TILE + ((sub >> 2) << 4) + (threadIdx.x >> 4);
    const int Yi = ty * TILE + ((sub & 3) << 4) + (threadIdx.x & 15);
    const float X = (float)Xi;
    const float Y = (float)Yi;

    const int cnt = t_cnt[ptile];
    const float4* __restrict__ pa = t_pa + ptile * N_G;
    const float4* __restrict__ pb = t_pb + ptile * N_G;
    const float*  __restrict__ pc = t_pc + ptile * N_G;

    float T = 1.0f;
    float C0 = 0.0f, C1 = 0.0f, C2 = 0.0f;

    for (int j = 0; j < cnt; j++) {
        const float4 A = __ldg(pa + j);          // px, py, ca', cbc'
        const float4 B = __ldg(pb + j);          // cd', log2(op), r, g
        const float  cb = __ldg(pc + j);         // b
        const float dx = X - A.x;
        const float dy = Y - A.y;
        float e = fmaf(A.z, dx * dx, B.y);
        e = fmaf(A.w, dx * dy, e);
        e = fmaf(B.x, dy * dy, e);
        const float alpha = fminf(fmaxf(ex2f(e), 0.01f), 0.99f);
        const float w = T * alpha;
        C0 = fmaf(w, B.z, C0);
        C1 = fmaf(w, B.w, C1);
        C2 = fmaf(w, cb, C2);
        T -= w;                                   // T *= (1 - alpha)
        if (__ballot_sync(0xffffffffu, T >= 1e-7f) == 0) break;
    }

    const int ob = (Xi * IMG_W + Yi) * 3;
    out[ob + 0] = C0;
    out[ob + 1] = C1;
    out[ob + 2] = C2;
}

// ---------------------------------------------------------------------------
extern "C" void kernel_launch(void* const* d_in, const int* in_sizes, int n_in,
                              void* d_out, int out_size)
{
    const float* pos2d   = (const float*)d_in[0];
    const float* cov2d   = (const float*)d_in[1];
    const float* opacity = (const float*)d_in[2];
    const float* color   = (const float*)d_in[3];
    float* out = (float*)d_out;

    rank_partial<<<dim3(N_G / BLOCK, NJB), BLOCK>>>(pos2d);
    scatter_kernel<<<N_G / BLOCK, BLOCK>>>(pos2d, cov2d, opacity, color);
    binning_kernel<<<NT * NT, BLOCK>>>();
    render_kernel<<<(NT * NT) * 16, BLOCK>>>(out);
}

// round 3
// speedup vs baseline: 2.2520x; 1.7668x over previous
#include <cuda_runtime.h>
#include <cuda_bf16.h>

#define N_G   4096
#define IMG_W 512
#define TILE  64
#define NT    8
#define BLOCK 256
#define NB    592                     // 148 SMs * 4 resident blocks
#define NJB   16
#define EXPSCALE (-0.72134752044f)    // -0.5 * log2(e)
#define L99      (-0.014500313f)      // log2(0.99)
#define RTHR_F   (1.0234444f)         // 9.2110 / 9  (far threshold on dist^2/radius^2)

// rank-ordered gaussian params
__device__ float4 g_geo[N_G];         // px, py, radius, 0
__device__ float4 g_la [N_G];         // px, py, ca*S, cbc*S
__device__ float4 g_lb [N_G];         // cd*S, log2(op), rthr2, r
__device__ float2 g_lc [N_G];         // g, b
__device__ int    g_prank[NJB][N_G];

// per-tile compacted depth-ordered lists
__device__ float4 t_la[64 * N_G];
__device__ float4 t_lb[64 * N_G];
__device__ float2 t_lc[64 * N_G];
__device__ int    t_cnt[64];

// monotonic ticket barrier counter (replay-safe: each run adds exactly 3*NB)
__device__ unsigned g_bar;

__device__ __forceinline__ float ex2f(float x) {
    float y; asm("ex2.approx.f32 %0, %1;" : "=f"(y) : "f"(x)); return y;
}

struct SM {
    float4 n0[BLOCK], n1[BLOCK], n2[BLOCK];
    float  n3[BLOCK];
    int    sF[BLOCK];
    float  sSr[BLOCK], sSg[BLOCK], sSb[BLOCK];
    int    jpos[BLOCK];
    int    wsum[8];
    float  wsf[24];
    float  tailSr, tailSg, tailSb, tailP;
};

// block-wide exclusive count of predicate; leading sync protects wsum reuse
__device__ __forceinline__ int scan_bool(bool p, int* wsum, int& tot) {
    __syncthreads();
    const unsigned bits = __ballot_sync(0xffffffffu, p);
    const int lane = threadIdx.x & 31, wd = threadIdx.x >> 5;
    if (lane == 0) wsum[wd] = __popc(bits);
    __syncthreads();
    int off = 0, t = 0;
#pragma unroll
    for (int w = 0; w < 8; w++) { int c = wsum[w]; if (w < wd) off += c; t += c; }
    tot = t;
    return off + __popc(bits & ((1u << lane) - 1u));
}

__device__ __forceinline__ void grid_sync() {
    __syncthreads();
    if (threadIdx.x == 0) {
        __threadfence();
        unsigned v = atomicAdd(&g_bar, 1u);
        unsigned target = (v / NB + 1u) * NB;
        while (*(volatile unsigned*)&g_bar < target) { }
        __threadfence();
    }
    __syncthreads();
}

__global__ void __launch_bounds__(BLOCK, 4)
fused_kernel(const float* __restrict__ pos2d, const float* __restrict__ cov2d,
             const float* __restrict__ opacity, const float* __restrict__ color,
             float* __restrict__ out)
{
    __shared__ SM sm;
    const int tid = threadIdx.x;
    const int bid = blockIdx.x;

    // ---------------- Phase 1: partial stable-rank counts ----------------
    if (bid < 256) {
        const int ibk = bid >> 4, jbk = bid & 15;
        const int i = ibk * BLOCK + tid;
        const float di = pos2d[i * 3 + 2];
        sm.sSr[tid] = pos2d[(jbk * BLOCK + tid) * 3 + 2];
        __syncthreads();
        int cnt = 0;
#pragma unroll 8
        for (int j = 0; j < BLOCK; j++) {
            const float dj = sm.sSr[j];
            cnt += (dj < di) || (dj == di && (jbk * BLOCK + j) < i);
        }
        g_prank[jbk][i] = cnt;
    }
    grid_sync();

    // ---------------- Phase 2: derive params, scatter by rank ----------------
    if (bid < 16) {
        const int i = bid * BLOCK + tid;
        int rank = 0;
#pragma unroll
        for (int b = 0; b < NJB; b++) rank += g_prank[b][i];

        const float a = cov2d[i * 4 + 0];
        const float b = cov2d[i * 4 + 1];
        const float c = cov2d[i * 4 + 2];
        const float d = cov2d[i * 4 + 3];
        const float trace = a + d;
        const float det   = a * d - b * c;
        const float term2 = 0.5f * sqrtf(fmaxf(trace * trace - 4.0f * det, 0.0f));
        const float radius = 3.0f * sqrtf(fmaxf(0.5f * trace - term2, 0.5f * trace + term2));
        const float inv_det = 1.0f / det;

        const float px = pos2d[i * 3 + 0];
        const float py = pos2d[i * 3 + 1];
        const float lop2 = __log2f(opacity[i]);
        const float cr = fmaxf(color[i * 3 + 0] + 0.5f, 0.0f);
        const float cg = fmaxf(color[i * 3 + 1] + 0.5f, 0.0f);
        const float cb = fmaxf(color[i * 3 + 2] + 0.5f, 0.0f);

        g_geo[rank] = make_float4(px, py, radius, 0.0f);
        g_la [rank] = make_float4(px, py, EXPSCALE * d * inv_det, EXPSCALE * -(b + c) * inv_det);
        g_lb [rank] = make_float4(EXPSCALE * a * inv_det, lop2, RTHR_F * radius * radius, cr);
        g_lc [rank] = make_float2(cg, cb);
    }
    grid_sync();

    // ---------------- Phase 3: per-tile binning (blocks 0..63) ----------------
    if (bid < 64) {
        const int tile = bid;
        const float left = (float)((tile >> 3) * TILE);
        const float top  = (float)((tile & 7) * TILE);
        int outbase = 0;
        for (int base = 0; base < N_G; base += BLOCK) {
            const int g = base + tid;
            const float4 geo = g_geo[g];
            const bool v = (geo.x + geo.z >= left) && (geo.x - geo.z < left + (float)TILE) &&
                           (geo.y + geo.z >= top)  && (geo.y - geo.z < top  + (float)TILE);
            int tot;
            const int pos = scan_bool(v, sm.wsum, tot);
            if (v) {
                const int o = tile * N_G + outbase + pos;
                t_la[o] = g_la[g];
                t_lb[o] = g_lb[g];
                t_lc[o] = g_lc[g];
            }
            outbase += tot;
        }
        if (tid == 0) t_cnt[tile] = outbase;
    }
    grid_sync();

    // ---------------- Phase 4: render (1024 subtiles, grid-strided) ----------------
    const int lane = tid & 31, wd = tid >> 5;
    for (int s = bid; s < 1024; s += NB) {
        const int ptile = s >> 4, sub = s & 15;
        const int X0 = (ptile >> 3) * TILE + ((sub >> 2) << 4);
        const int Y0 = (ptile & 7) * TILE + ((sub & 3) << 4);
        const int Xi = X0 + (tid >> 4);
        const int Yi = Y0 + (tid & 15);
        const float X = (float)Xi, Y = (float)Yi;
        const float rx0 = (float)X0, rx1 = (float)(X0 + 15);
        const float ry0 = (float)Y0, ry1 = (float)(Y0 + 15);

        const int cnt = t_cnt[ptile];
        const float4* __restrict__ LA = t_la + ptile * N_G;
        const float4* __restrict__ LB = t_lb + ptile * N_G;
        const float2* __restrict__ LC = t_lc + ptile * N_G;

        float T = 1.0f, C0 = 0.0f, C1 = 0.0f, C2 = 0.0f;

        for (int c0 = 0; c0 < cnt; c0 += BLOCK) {
            const int L = min(BLOCK, cnt - c0);
            const bool valid = tid < L;
            float4 la = make_float4(0,0,0,0), lb = make_float4(0,0,0,0);
            float2 lc = make_float2(0,0);
            bool isfar = false;
            if (valid) {
                la = LA[c0 + tid]; lb = LB[c0 + tid]; lc = LC[c0 + tid];
                const float cx = fminf(fmaxf(la.x, rx0), rx1);
                const float cy = fminf(fmaxf(la.y, ry0), ry1);
                const float ddx = la.x - cx, ddy = la.y - cy;
                isfar = (ddx * ddx + ddy * ddy) > lb.z;   // dist^2 > 1.02344*r^2 -> alpha==0.01 everywhere
            }
            int Ftot;
            const int F = scan_bool(isfar, sm.wsum, Ftot);   // exclusive far count

            // far gaussian weight 0.01 * 0.99^F, color-weighted exclusive block scan
            const float pw = isfar ? 0.01f * ex2f((float)F * L99) : 0.0f;
            const float vr = pw * lb.w, vg = pw * lc.x, vb = pw * lc.y;
            float ir = vr, ig = vg, ibb = vb;
#pragma unroll
            for (int dd = 1; dd < 32; dd <<= 1) {
                const float tr = __shfl_up_sync(0xffffffffu, ir, dd);
                const float tg = __shfl_up_sync(0xffffffffu, ig, dd);
                const float tb = __shfl_up_sync(0xffffffffu, ibb, dd);
                if (lane >= dd) { ir += tr; ig += tg; ibb += tb; }
            }
            __syncthreads();
            if (lane == 31) { sm.wsf[wd*3] = ir; sm.wsf[wd*3+1] = ig; sm.wsf[wd*3+2] = ibb; }
            __syncthreads();
            float offr = 0, offg = 0, offb = 0, totr = 0, totg = 0, totb = 0;
#pragma unroll
            for (int w = 0; w < 8; w++) {
                const float xr = sm.wsf[w*3], xg = sm.wsf[w*3+1], xb = sm.wsf[w*3+2];
                if (w < wd) { offr += xr; offg += xg; offb += xb; }
                totr += xr; totg += xg; totb += xb;
            }
            const float Sr = offr + ir - vr, Sg = offg + ig - vg, Sb = offb + ibb - vb;

            sm.sF[tid] = F;
            sm.sSr[tid] = Sr; sm.sSg[tid] = Sg; sm.sSb[tid] = Sb;
            const bool isnear = valid && !isfar;
            const int ncnt = L - Ftot;
            const int nidx = tid - F;
            if (isnear) sm.jpos[nidx] = tid;
            __syncthreads();

            if (isnear) {
                float Fp = 0.0f, Spr = 0.0f, Spg = 0.0f, Spb = 0.0f;
                if (nidx > 0) {
                    const int pp = sm.jpos[nidx - 1];
                    Fp = (float)sm.sF[pp]; Spr = sm.sSr[pp]; Spg = sm.sSg[pp]; Spb = sm.sSb[pp];
                }
                const float inv = ex2f(-Fp * L99);
                sm.n0[nidx] = la;
                sm.n1[nidx] = make_float4(lb.x, lb.y, lb.w, lc.x);     // cd', lop2, r, g
                sm.n2[nidx] = make_float4((Sr - Spr) * inv, (Sg - Spg) * inv,
                                          (Sb - Spb) * inv, ex2f(((float)F - Fp) * L99));
                sm.n3[nidx] = lc.y;                                    // b
            }
            if (tid == 0) {
                if (ncnt > 0) {
                    const int pl = sm.jpos[ncnt - 1];
                    const float Fp = (float)sm.sF[pl];
                    const float inv = ex2f(-Fp * L99);
                    sm.tailSr = (totr - sm.sSr[pl]) * inv;
                    sm.tailSg = (totg - sm.sSg[pl]) * inv;
                    sm.tailSb = (totb - sm.sSb[pl]) * inv;
                    sm.tailP  = ex2f(((float)Ftot - Fp) * L99);
                } else {
                    sm.tailSr = totr; sm.tailSg = totg; sm.tailSb = totb;
                    sm.tailP  = ex2f((float)Ftot * L99);
                }
            }
            __syncthreads();

            // per-pixel composite: near gaussians with aggregated far-gaps
            for (int t = 0; t < ncnt; t++) {
                const float4 f0 = sm.n0[t];
                const float4 f1 = sm.n1[t];
                const float4 f2 = sm.n2[t];
                const float  b3 = sm.n3[t];
                C0 = fmaf(T, f2.x, C0); C1 = fmaf(T, f2.y, C1); C2 = fmaf(T, f2.z, C2);
                T *= f2.w;
                const float dx = X - f0.x, dy = Y - f0.y;
                float e = fmaf(f0.z, dx * dx, f1.y);
                e = fmaf(f0.w, dx * dy, e);
                e = fmaf(f1.x, dy * dy, e);
                const float al = fminf(fmaxf(ex2f(e), 0.01f), 0.99f);
                const float w = T * al;
                C0 = fmaf(w, f1.z, C0); C1 = fmaf(w, f1.w, C1); C2 = fmaf(w, b3, C2);
                T -= w;
            }
            C0 = fmaf(T, sm.tailSr, C0); C1 = fmaf(T, sm.tailSg, C1); C2 = fmaf(T, sm.tailSb, C2);
            T *= sm.tailP;
        }

        const int ob = (Xi * IMG_W + Yi) * 3;
        out[ob + 0] = C0;
        out[ob + 1] = C1;
        out[ob + 2] = C2;
    }
}

extern "C" void kernel_launch(void* const* d_in, const int* in_sizes, int n_in,
                              void* d_out, int out_size)
{
    const float* pos2d   = (const float*)d_in[0];
    const float* cov2d   = (const float*)d_in[1];
    const float* opacity = (const float*)d_in[2];
    const float* color   = (const float*)d_in[3];
    float* out = (float*)d_out;

    fused_kernel<<<NB, BLOCK>>>(pos2d, cov2d, opacity, color, out);
}